// round 9
// baseline (speedup 1.0000x reference)
#include <cuda_runtime.h>
#include <float.h>

#define Bdim 16
#define Npts 4096
#define Mq   1024
#define CIN  64
#define KNN  32
#define CH   (CIN + 3)   // 67 input channels (rel xyz + features)
#define H1   64
#define H2   128

// scratch: neighbor indices + precomputed feature part of layer 1
__device__ int   g_nn[Bdim * Mq * KNN];
__device__ float g_h1pre[Bdim * Npts * H1];   // feat @ W1[3:] + b1 (pre-relu)

typedef unsigned long long ull;

// ---------------------------------------------------------------------------
// helpers
// ---------------------------------------------------------------------------
__device__ __forceinline__ ull pack2(float lo, float hi) {
    ull r;
    asm("mov.b64 %0, {%1, %2};" : "=l"(r) : "f"(lo), "f"(hi));
    return r;
}
__device__ __forceinline__ void unpack2(ull v, float& lo, float& hi) {
    asm("mov.b64 {%0, %1}, %2;" : "=f"(lo), "=f"(hi) : "l"(v));
}
__device__ __forceinline__ ull fma2(ull a, ull b, ull c) {
    ull r;
    asm("fma.rn.f32x2 %0, %1, %2, %3;" : "=l"(r) : "l"(a), "l"(b), "l"(c));
    return r;
}

// idx dtype detection: int64 values < 4096 -> all odd 32-bit words are 0.
__device__ __forceinline__ int idx_is64(const void* idxp) {
    const int* p = (const int*)idxp;
    int acc = p[1] | p[3] | p[5] | p[7] | p[9] | p[11] | p[13] | p[15];
    return acc == 0;
}
__device__ __forceinline__ long long load_idx2(const void* idxp, int i, int is64) {
    return is64 ? ((const long long*)idxp)[i] : (long long)((const int*)idxp)[i];
}

// ordered-float transform: total order on float bits as unsigned
__device__ __forceinline__ unsigned ordflt(float f) {
    unsigned fb = __float_as_uint(f);
    return fb ^ ((unsigned)((int)fb >> 31) | 0x80000000u);
}

// ---------------------------------------------------------------------------
// KNN kernel v5: warp per query, 2-pass radix select, 16 warps/block,
// 4x ILP unroll, atomic-based rare-path compaction.
// vs v4: NBIN 2048 -> 1024 so smem drops 144 -> 112 KB/block, enabling
// 2 blocks/SM (8 warps/SMSP) to cover the LDS/match_any latency chains.
// ---------------------------------------------------------------------------
#define KQPB      16     // queries (warps) per block
#define KTPB      512
#define NBIN      1024
#define ORD_SHIFT 22     // 32 - log2(NBIN)

__global__ void __launch_bounds__(KTPB, 2)
knn_kernel(const float* __restrict__ pos,
           const void*  __restrict__ idxp,
           float* __restrict__ out_posq)
{
    __shared__ __align__(16) float4 sp[Npts];                 // 64 KB
    __shared__ __align__(16) unsigned short hist[KQPB][NBIN]; // 32 KB
    __shared__ __align__(16) ull blist[KQPB][128];            // 16 KB
    __shared__ int scnt[KQPB], bcnt[KQPB];

    const int tid  = threadIdx.x;
    const int w    = tid >> 5;
    const int lane = tid & 31;
    const unsigned lt = (1u << lane) - 1u;
    const int b    = blockIdx.x >> 6;                 // 64 blocks per batch
    const int m    = ((blockIdx.x & 63) << 4) | w;
    const int q    = (b << 10) | m;

    const float* posb = pos + b * Npts * 3;

    // zero this warp's histogram (2 KB -> 4 uint4 stores per lane)
    {
        uint4* hz = (uint4*)hist[w];
        uint4 z = make_uint4(0, 0, 0, 0);
#pragma unroll
        for (int i = lane; i < NBIN * 2 / 16; i += 32) hz[i] = z;
    }
    if (lane == 0) { scnt[w] = 0; bcnt[w] = 0; }

    // stage the full point tile once
    for (int i = tid; i < Npts; i += KTPB) {
        float px = posb[i * 3 + 0];
        float py = posb[i * 3 + 1];
        float pz = posb[i * 3 + 2];
        sp[i] = make_float4(px, py, pz, px * px + py * py + pz * pz);
    }

    const int is64 = idx_is64(idxp);
    const long long qi = load_idx2(idxp, q, is64);
    const float qx = posb[qi * 3 + 0];
    const float qy = posb[qi * 3 + 1];
    const float qz = posb[qi * 3 + 2];
    const float qn = qx * qx + qy * qy + qz * qz;

    if (lane == 0) {
        out_posq[q * 3 + 0] = qx;
        out_posq[q * 3 + 1] = qy;
        out_posq[q * 3 + 2] = qz;
    }
    __syncthreads();

    // ---------------- pass 1: histogram (4x ILP) ----------------
    for (int o = 0; o < Npts; o += 128) {
        unsigned bin[4];
#pragma unroll
        for (int u = 0; u < 4; ++u) {
            float4 p = sp[o + u * 32 + lane];
            float d2 = fmaf(-2.0f, fmaf(qx, p.x, fmaf(qy, p.y, qz * p.z)), qn + p.w);
            bin[u] = ordflt(d2) >> ORD_SHIFT;
        }
#pragma unroll
        for (int u = 0; u < 4; ++u) {
            unsigned mm = __match_any_sync(0xffffffffu, bin[u]);
            if ((mm & lt) == 0)   // lowest lane of each equal-bin group
                hist[w][bin[u]] = (unsigned short)(hist[w][bin[u]] + (unsigned)__popc(mm));
        }
    }
    __syncwarp();

    // ---------------- boundary-bin search ----------------
    int B = 0; unsigned below = 0;
    {
        const int base = lane * (NBIN / 32);
        unsigned s = 0;
#pragma unroll 8
        for (int j = 0; j < NBIN / 32; ++j) s += hist[w][base + j];
        unsigned incl = s;
#pragma unroll
        for (int d_ = 1; d_ < 32; d_ <<= 1) {
            unsigned t_ = __shfl_up_sync(0xffffffffu, incl, d_);
            if (lane >= d_) incl += t_;
        }
        unsigned excl = incl - s;
        unsigned bal = __ballot_sync(0xffffffffu, incl >= (unsigned)KNN);
        int L = __ffs(bal) - 1;
        if (lane == L) {
            unsigned cum = excl;
            for (int j = 0; j < NBIN / 32; ++j) {
                unsigned c = hist[w][base + j];
                if (cum + c >= (unsigned)KNN) { B = base + j; below = cum; break; }
                cum += c;
            }
        }
        B = __shfl_sync(0xffffffffu, B, L);
        below = __shfl_sync(0xffffffffu, below, L);
    }

    // ---------------- pass 2: collect (4x ILP, rare-path atomics) ----------
    int* dst = g_nn + q * KNN;
    const unsigned uB = (unsigned)B;

    for (int o = 0; o < Npts; o += 128) {
        unsigned orf[4];
#pragma unroll
        for (int u = 0; u < 4; ++u) {
            float4 p = sp[o + u * 32 + lane];
            float d2 = fmaf(-2.0f, fmaf(qx, p.x, fmaf(qy, p.y, qz * p.z)), qn + p.w);
            orf[u] = ordflt(d2);
        }
#pragma unroll
        for (int u = 0; u < 4; ++u) {
            unsigned bin = orf[u] >> ORD_SHIFT;
            if (bin <= uB) {                       // rare (<~60/4096 per warp)
                int i = o + u * 32 + lane;
                if (bin < uB) {
                    int p_ = atomicAdd(&scnt[w], 1);
                    dst[p_] = i;
                } else {
                    int p_ = atomicAdd(&bcnt[w], 1);
                    if (p_ < 128)
                        blist[w][p_] = (((ull)orf[u]) << 32) | (unsigned)i;
                }
            }
        }
    }
    __syncwarp();

    const int outn = scnt[w];       // == below
    const int brun = bcnt[w];
    const int r = KNN - outn;

    if (brun <= 128) {
        // warp-cooperative selection of r smallest (key,idx) from the list
        ull e[4];
#pragma unroll
        for (int t_ = 0; t_ < 4; ++t_) {
            int id = t_ * 32 + lane;
            e[t_] = (id < brun) ? blist[w][id] : ~0ull;
        }
        for (int s_ = 0; s_ < r; ++s_) {
            ull lm = e[0];
            lm = e[1] < lm ? e[1] : lm;
            lm = e[2] < lm ? e[2] : lm;
            lm = e[3] < lm ? e[3] : lm;
            ull wm = lm;
#pragma unroll
            for (int d_ = 16; d_ > 0; d_ >>= 1) {
                ull o = __shfl_xor_sync(0xffffffffu, wm, d_);
                wm = o < wm ? o : wm;
            }
            if (lane == 0) dst[outn + s_] = (int)(wm & 0xffffffffu);
#pragma unroll
            for (int t_ = 0; t_ < 4; ++t_)
                if (e[t_] == wm) e[t_] = ~0ull;
        }
    } else {
        // cold fallback (pathological tie density): repeated warp-min rescans
        ull last = 0ull;
        for (int s_ = 0; s_ < r; ++s_) {
            ull best = ~0ull;
            for (int i = lane; i < Npts; i += 32) {
                float4 p = sp[i];
                float d2 = fmaf(-2.0f, fmaf(qx, p.x, fmaf(qy, p.y, qz * p.z)), qn + p.w);
                unsigned orf_ = ordflt(d2);
                if ((int)(orf_ >> ORD_SHIFT) == B) {
                    ull key = (((ull)orf_) << 32) | (unsigned)i;
                    if (key > last && key < best) best = key;
                }
            }
#pragma unroll
            for (int d_ = 16; d_ > 0; d_ >>= 1) {
                ull o = __shfl_xor_sync(0xffffffffu, best, d_);
                best = o < best ? o : best;
            }
            if (lane == 0) dst[outn + s_] = (int)(best & 0xffffffffu);
            last = best;
        }
    }
}

// ---------------------------------------------------------------------------
// Precompute kernel: g_h1pre[n][j] = feat[n] @ W1[3:67] + b1   (pre-relu)
// Plain register-tiled GEMM, 128 rows/block, thread tile 4x8 with f32x2.
// ---------------------------------------------------------------------------
#define PRE_TPB 256

__global__ void __launch_bounds__(PRE_TPB)
pre_kernel(const float* __restrict__ feat,
           const float* __restrict__ W1,
           const float* __restrict__ b1)
{
    __shared__ __align__(16) float fT[CIN * 128];   // featT[c][row]  32 KB
    __shared__ __align__(16) float Wf[CIN * H1];    // W1 rows 3..66  16 KB

    const int t  = threadIdx.x;
    const int n0 = blockIdx.x * 128;

    // stage Wf: Wf[i] = W1[192 + i] (rows 3..66, linear)
    for (int i = t; i < CIN * H1 / 4; i += PRE_TPB)
        ((float4*)Wf)[i] = *(const float4*)(W1 + 192 + i * 4);

    // stage feat transposed
    {
        const int row  = t >> 1;
        const int half = t & 1;
        const float4* f4 = (const float4*)(feat + (size_t)(n0 + row) * CIN);
#pragma unroll
        for (int r_ = 0; r_ < 8; ++r_) {
            float4 v = f4[half * 8 + r_];
            int c0 = half * 32 + r_ * 4;
            fT[(c0 + 0) * 128 + row] = v.x;
            fT[(c0 + 1) * 128 + row] = v.y;
            fT[(c0 + 2) * 128 + row] = v.z;
            fT[(c0 + 3) * 128 + row] = v.w;
        }
    }
    __syncthreads();

    const int tk = t & 31;
    const int tj = t >> 5;

    ull acc[4][4];
    {
        float4 bA = ((const float4*)b1)[tj * 2];
        float4 bB = ((const float4*)b1)[tj * 2 + 1];
        ull bp[4] = { pack2(bA.x, bA.y), pack2(bA.z, bA.w),
                      pack2(bB.x, bB.y), pack2(bB.z, bB.w) };
#pragma unroll
        for (int r_ = 0; r_ < 4; ++r_)
#pragma unroll
            for (int p_ = 0; p_ < 4; ++p_) acc[r_][p_] = bp[p_];
    }

    for (int c = 0; c < CIN; ++c) {
        float4 xv = *(const float4*)&fT[c * 128 + tk * 4];
        ulonglong2 wA = *(const ulonglong2*)&Wf[c * H1 + tj * 8];
        ulonglong2 wB = *(const ulonglong2*)&Wf[c * H1 + tj * 8 + 4];
        ull x0 = pack2(xv.x, xv.x);
        ull x1 = pack2(xv.y, xv.y);
        ull x2 = pack2(xv.z, xv.z);
        ull x3 = pack2(xv.w, xv.w);
        acc[0][0] = fma2(x0, wA.x, acc[0][0]);
        acc[0][1] = fma2(x0, wA.y, acc[0][1]);
        acc[0][2] = fma2(x0, wB.x, acc[0][2]);
        acc[0][3] = fma2(x0, wB.y, acc[0][3]);
        acc[1][0] = fma2(x1, wA.x, acc[1][0]);
        acc[1][1] = fma2(x1, wA.y, acc[1][1]);
        acc[1][2] = fma2(x1, wB.x, acc[1][2]);
        acc[1][3] = fma2(x1, wB.y, acc[1][3]);
        acc[2][0] = fma2(x2, wA.x, acc[2][0]);
        acc[2][1] = fma2(x2, wA.y, acc[2][1]);
        acc[2][2] = fma2(x2, wB.x, acc[2][2]);
        acc[2][3] = fma2(x2, wB.y, acc[2][3]);
        acc[3][0] = fma2(x3, wA.x, acc[3][0]);
        acc[3][1] = fma2(x3, wA.y, acc[3][1]);
        acc[3][2] = fma2(x3, wB.x, acc[3][2]);
        acc[3][3] = fma2(x3, wB.y, acc[3][3]);
    }

#pragma unroll
    for (int r_ = 0; r_ < 4; ++r_)
#pragma unroll
        for (int p_ = 0; p_ < 4; ++p_)
            *(ull*)&g_h1pre[(size_t)(n0 + tk * 4 + r_) * H1 + tj * 8 + p_ * 2]
                = acc[r_][p_];
}

// ---------------------------------------------------------------------------
// MLP v3: gather precomputed h1_pre + xyz correction + relu, then phase-2
// register-tiled GEMM [128x64]@[64x128] with f32x2, max-pool epilogue.
// ---------------------------------------------------------------------------
#define MQPB    4
#define MLP_TPB 256

__global__ void __launch_bounds__(MLP_TPB, 2)
mlp_kernel(const float* __restrict__ pos,
           const float* __restrict__ W1,
           const float* __restrict__ W2,
           const float* __restrict__ b2,
           const void*  __restrict__ idxp,
           float* __restrict__ outp)
{
    __shared__ __align__(16) float W2s[H1 * H2];    // 32 KB
    __shared__ __align__(16) float h1T[H1 * 128];   // 32 KB; later redscr[32][129]
    __shared__ __align__(16) float W1x[3 * H1];     // xyz rows of W1

    const int t  = threadIdx.x;
    const int q0 = blockIdx.x * MQPB;
    const int b  = q0 >> 10;

    // ---- stage weights ----
    for (int i = t; i < H1 * H2 / 4; i += MLP_TPB)
        ((float4*)W2s)[i] = ((const float4*)W2)[i];
    if (t < 48) ((float4*)W1x)[t] = ((const float4*)W1)[t];
    __syncthreads();   // gather below reads W1x from smem

    // ---- gather h1_pre rows + xyz correction + relu, transposed store ----
    {
        const int row  = t >> 1;        // 0..127
        const int half = t & 1;
        const int lq   = row >> 5;
        const int k    = row & 31;
        const int q    = q0 + lq;

        const float* posb = pos + (size_t)b * Npts * 3;
        const int is64 = idx_is64(idxp);
        const long long qi = load_idx2(idxp, q, is64);
        const int n = g_nn[(size_t)q * KNN + k];

        const float x0 = posb[n * 3 + 0] - posb[qi * 3 + 0];
        const float x1 = posb[n * 3 + 1] - posb[qi * 3 + 1];
        const float x2 = posb[n * 3 + 2] - posb[qi * 3 + 2];

        const float4* pre4 = (const float4*)(g_h1pre + (size_t)((b << 12) + n) * H1);
#pragma unroll
        for (int r_ = 0; r_ < 8; ++r_) {
            float4 v = pre4[half * 8 + r_];
            int j0 = half * 32 + r_ * 4;
            float4 wx = *(const float4*)&W1x[j0];
            float4 wy = *(const float4*)&W1x[H1 + j0];
            float4 wz = *(const float4*)&W1x[2 * H1 + j0];
            v.x = fmaxf(fmaf(x0, wx.x, fmaf(x1, wy.x, fmaf(x2, wz.x, v.x))), 0.0f);
            v.y = fmaxf(fmaf(x0, wx.y, fmaf(x1, wy.y, fmaf(x2, wz.y, v.y))), 0.0f);
            v.z = fmaxf(fmaf(x0, wx.z, fmaf(x1, wy.z, fmaf(x2, wz.z, v.z))), 0.0f);
            v.w = fmaxf(fmaf(x0, wx.w, fmaf(x1, wy.w, fmaf(x2, wz.w, v.w))), 0.0f);
            h1T[(j0 + 0) * 128 + row] = v.x;
            h1T[(j0 + 1) * 128 + row] = v.y;
            h1T[(j0 + 2) * 128 + row] = v.z;
            h1T[(j0 + 3) * 128 + row] = v.w;
        }
    }
    __syncthreads();

    // ---- phase 2: tile 4 rows (tk) x 16 cols (td), f32x2 over d-pairs ----
    const int tk = t & 31;
    const int td = t >> 5;
    ull acc2[4][8];
#pragma unroll
    for (int r_ = 0; r_ < 4; ++r_)
#pragma unroll
        for (int p_ = 0; p_ < 8; ++p_) acc2[r_][p_] = 0ull;

    for (int j = 0; j < H1; ++j) {
        float4 hv = *(const float4*)&h1T[j * 128 + tk * 4];
        const ulonglong2* wp = (const ulonglong2*)&W2s[j * H2 + td * 16];
        ulonglong2 wA = wp[0], wB = wp[1], wC = wp[2], wD = wp[3];
        ull h0 = pack2(hv.x, hv.x);
        ull h1v = pack2(hv.y, hv.y);
        ull h2 = pack2(hv.z, hv.z);
        ull h3 = pack2(hv.w, hv.w);
        acc2[0][0] = fma2(h0, wA.x, acc2[0][0]);
        acc2[0][1] = fma2(h0, wA.y, acc2[0][1]);
        acc2[0][2] = fma2(h0, wB.x, acc2[0][2]);
        acc2[0][3] = fma2(h0, wB.y, acc2[0][3]);
        acc2[0][4] = fma2(h0, wC.x, acc2[0][4]);
        acc2[0][5] = fma2(h0, wC.y, acc2[0][5]);
        acc2[0][6] = fma2(h0, wD.x, acc2[0][6]);
        acc2[0][7] = fma2(h0, wD.y, acc2[0][7]);
        acc2[1][0] = fma2(h1v, wA.x, acc2[1][0]);
        acc2[1][1] = fma2(h1v, wA.y, acc2[1][1]);
        acc2[1][2] = fma2(h1v, wB.x, acc2[1][2]);
        acc2[1][3] = fma2(h1v, wB.y, acc2[1][3]);
        acc2[1][4] = fma2(h1v, wC.x, acc2[1][4]);
        acc2[1][5] = fma2(h1v, wC.y, acc2[1][5]);
        acc2[1][6] = fma2(h1v, wD.x, acc2[1][6]);
        acc2[1][7] = fma2(h1v, wD.y, acc2[1][7]);
        acc2[2][0] = fma2(h2, wA.x, acc2[2][0]);
        acc2[2][1] = fma2(h2, wA.y, acc2[2][1]);
        acc2[2][2] = fma2(h2, wB.x, acc2[2][2]);
        acc2[2][3] = fma2(h2, wB.y, acc2[2][3]);
        acc2[2][4] = fma2(h2, wC.x, acc2[2][4]);
        acc2[2][5] = fma2(h2, wC.y, acc2[2][5]);
        acc2[2][6] = fma2(h2, wD.x, acc2[2][6]);
        acc2[2][7] = fma2(h2, wD.y, acc2[2][7]);
        acc2[3][0] = fma2(h3, wA.x, acc2[3][0]);
        acc2[3][1] = fma2(h3, wA.y, acc2[3][1]);
        acc2[3][2] = fma2(h3, wB.x, acc2[3][2]);
        acc2[3][3] = fma2(h3, wB.y, acc2[3][3]);
        acc2[3][4] = fma2(h3, wC.x, acc2[3][4]);
        acc2[3][5] = fma2(h3, wC.y, acc2[3][5]);
        acc2[3][6] = fma2(h3, wD.x, acc2[3][6]);
        acc2[3][7] = fma2(h3, wD.y, acc2[3][7]);
    }
    __syncthreads();   // h1T reads done; reuse as reduction scratch

    // ---- epilogue: per-thread max over 4 rows, scratch, final reduce ----
    float* redscr = h1T;   // [32][129]
#pragma unroll
    for (int p_ = 0; p_ < 8; ++p_) {
        float e0, o0, e1, o1, e2, o2, e3, o3;
        unpack2(acc2[0][p_], e0, o0);
        unpack2(acc2[1][p_], e1, o1);
        unpack2(acc2[2][p_], e2, o2);
        unpack2(acc2[3][p_], e3, o3);
        float me = fmaxf(fmaxf(e0, e1), fmaxf(e2, e3));
        float mo = fmaxf(fmaxf(o0, o1), fmaxf(o2, o3));
        redscr[tk * 129 + td * 16 + p_ * 2 + 0] = me;
        redscr[tk * 129 + td * 16 + p_ * 2 + 1] = mo;
    }
    __syncthreads();

    for (int o = t; o < MQPB * H2; o += MLP_TPB) {
        int lq = o >> 7;
        int d  = o & 127;
        float mx = -FLT_MAX;
#pragma unroll
        for (int s_ = 0; s_ < 8; ++s_)
            mx = fmaxf(mx, redscr[(lq * 8 + s_) * 129 + d]);
        outp[(size_t)(q0 + lq) * H2 + d] = fmaxf(mx + b2[d], 0.0f);
    }
}

// ---------------------------------------------------------------------------
// launcher
// ---------------------------------------------------------------------------
extern "C" void kernel_launch(void* const* d_in, const int* in_sizes, int n_in,
                              void* d_out, int out_size)
{
    const float* pos  = (const float*)d_in[0];   // [16,4096,3]
    const float* feat = (const float*)d_in[1];   // [16,4096,64]
    const float* W1   = (const float*)d_in[2];   // [67,64]
    const float* b1   = (const float*)d_in[3];   // [64]
    const float* W2   = (const float*)d_in[4];   // [64,128]
    const float* b2   = (const float*)d_in[5];   // [128]
    const void*  idxp = d_in[6];                 // [16,1024] int64 or int32

    float* out_posq = (float*)d_out;                          // 16*1024*3
    float* out_feat = (float*)d_out + (size_t)Bdim * Mq * 3;  // 16*1024*128

    pre_kernel<<<(Bdim * Npts) / 128, PRE_TPB>>>(feat, W1, b1);

    knn_kernel<<<Bdim * (Mq / KQPB), KTPB>>>(pos, idxp, out_posq);

    mlp_kernel<<<(Bdim * Mq) / MQPB, MLP_TPB>>>(pos, W1, W2, b2, idxp, out_feat);
}

// round 12
// speedup vs baseline: 1.3585x; 1.3585x over previous
#include <cuda_runtime.h>
#include <float.h>

#define Bdim 16
#define Npts 4096
#define Mq   1024
#define CIN  64
#define KNN  32
#define CH   (CIN + 3)   // 67 input channels (rel xyz + features)
#define H1   64
#define H2   128

// scratch: neighbor indices + precomputed feature part of layer 1
__device__ int   g_nn[Bdim * Mq * KNN];
__device__ float g_h1pre[Bdim * Npts * H1];   // feat @ W1[3:] + b1 (pre-relu)

typedef unsigned long long ull;

// ---------------------------------------------------------------------------
// helpers
// ---------------------------------------------------------------------------
__device__ __forceinline__ ull pack2(float lo, float hi) {
    ull r;
    asm("mov.b64 %0, {%1, %2};" : "=l"(r) : "f"(lo), "f"(hi));
    return r;
}
__device__ __forceinline__ void unpack2(ull v, float& lo, float& hi) {
    asm("mov.b64 {%0, %1}, %2;" : "=f"(lo), "=f"(hi) : "l"(v));
}
__device__ __forceinline__ ull fma2(ull a, ull b, ull c) {
    ull r;
    asm("fma.rn.f32x2 %0, %1, %2, %3;" : "=l"(r) : "l"(a), "l"(b), "l"(c));
    return r;
}

// idx dtype detection: int64 values < 4096 -> all odd 32-bit words are 0.
__device__ __forceinline__ int idx_is64(const void* idxp) {
    const int* p = (const int*)idxp;
    int acc = p[1] | p[3] | p[5] | p[7] | p[9] | p[11] | p[13] | p[15];
    return acc == 0;
}
__device__ __forceinline__ long long load_idx2(const void* idxp, int i, int is64) {
    return is64 ? ((const long long*)idxp)[i] : (long long)((const int*)idxp)[i];
}

// ordered-float transform: total order on float bits as unsigned
__device__ __forceinline__ unsigned ordflt(float f) {
    unsigned fb = __float_as_uint(f);
    return fb ^ ((unsigned)((int)fb >> 31) | 0x80000000u);
}

// ---------------------------------------------------------------------------
// KNN kernel v6 = R8's v4 (NBIN 2048, natural regs, 1 block/SM) with the
// pass loops widened from 4x to 8x ILP. R9's forced-occupancy variant
// regressed (64-reg cap -> spills); reverted.
// ---------------------------------------------------------------------------
#define KQPB      16     // queries (warps) per block
#define KTPB      512
#define NBIN      2048
#define ORD_SHIFT 21     // 32 - log2(NBIN)

__global__ void __launch_bounds__(KTPB)
knn_kernel(const float* __restrict__ pos,
           const void*  __restrict__ idxp,
           float* __restrict__ out_posq)
{
    __shared__ __align__(16) float4 sp[Npts];                 // 64 KB
    __shared__ __align__(16) unsigned short hist[KQPB][NBIN]; // 64 KB
    __shared__ __align__(16) ull blist[KQPB][128];            // 16 KB
    __shared__ int scnt[KQPB], bcnt[KQPB];

    const int tid  = threadIdx.x;
    const int w    = tid >> 5;
    const int lane = tid & 31;
    const unsigned lt = (1u << lane) - 1u;
    const int b    = blockIdx.x >> 6;                 // 64 blocks per batch
    const int m    = ((blockIdx.x & 63) << 4) | w;
    const int q    = (b << 10) | m;

    const float* posb = pos + b * Npts * 3;

    // zero this warp's histogram (4 KB -> 8 uint4 stores per lane)
    {
        uint4* hz = (uint4*)hist[w];
        uint4 z = make_uint4(0, 0, 0, 0);
#pragma unroll
        for (int i = lane; i < NBIN * 2 / 16; i += 32) hz[i] = z;
    }
    if (lane == 0) { scnt[w] = 0; bcnt[w] = 0; }

    // stage the full point tile once
    for (int i = tid; i < Npts; i += KTPB) {
        float px = posb[i * 3 + 0];
        float py = posb[i * 3 + 1];
        float pz = posb[i * 3 + 2];
        sp[i] = make_float4(px, py, pz, px * px + py * py + pz * pz);
    }

    const int is64 = idx_is64(idxp);
    const long long qi = load_idx2(idxp, q, is64);
    const float qx = posb[qi * 3 + 0];
    const float qy = posb[qi * 3 + 1];
    const float qz = posb[qi * 3 + 2];
    const float qn = qx * qx + qy * qy + qz * qz;

    if (lane == 0) {
        out_posq[q * 3 + 0] = qx;
        out_posq[q * 3 + 1] = qy;
        out_posq[q * 3 + 2] = qz;
    }
    __syncthreads();

    // ---------------- pass 1: histogram (8x ILP) ----------------
    for (int o = 0; o < Npts; o += 256) {
        unsigned bin[8];
#pragma unroll
        for (int u = 0; u < 8; ++u) {
            float4 p = sp[o + u * 32 + lane];
            float d2 = fmaf(-2.0f, fmaf(qx, p.x, fmaf(qy, p.y, qz * p.z)), qn + p.w);
            bin[u] = ordflt(d2) >> ORD_SHIFT;
        }
#pragma unroll
        for (int u = 0; u < 8; ++u) {
            unsigned mm = __match_any_sync(0xffffffffu, bin[u]);
            if ((mm & lt) == 0)   // lowest lane of each equal-bin group
                hist[w][bin[u]] = (unsigned short)(hist[w][bin[u]] + (unsigned)__popc(mm));
        }
    }
    __syncwarp();

    // ---------------- boundary-bin search ----------------
    int B = 0; unsigned below = 0;
    {
        const int base = lane * (NBIN / 32);
        unsigned s = 0;
#pragma unroll 8
        for (int j = 0; j < NBIN / 32; ++j) s += hist[w][base + j];
        unsigned incl = s;
#pragma unroll
        for (int d_ = 1; d_ < 32; d_ <<= 1) {
            unsigned t_ = __shfl_up_sync(0xffffffffu, incl, d_);
            if (lane >= d_) incl += t_;
        }
        unsigned excl = incl - s;
        unsigned bal = __ballot_sync(0xffffffffu, incl >= (unsigned)KNN);
        int L = __ffs(bal) - 1;
        if (lane == L) {
            unsigned cum = excl;
            for (int j = 0; j < NBIN / 32; ++j) {
                unsigned c = hist[w][base + j];
                if (cum + c >= (unsigned)KNN) { B = base + j; below = cum; break; }
                cum += c;
            }
        }
        B = __shfl_sync(0xffffffffu, B, L);
        below = __shfl_sync(0xffffffffu, below, L);
    }

    // ---------------- pass 2: collect (8x ILP, rare-path atomics) ----------
    int* dst = g_nn + q * KNN;
    const unsigned uB = (unsigned)B;

    for (int o = 0; o < Npts; o += 256) {
        unsigned orf[8];
#pragma unroll
        for (int u = 0; u < 8; ++u) {
            float4 p = sp[o + u * 32 + lane];
            float d2 = fmaf(-2.0f, fmaf(qx, p.x, fmaf(qy, p.y, qz * p.z)), qn + p.w);
            orf[u] = ordflt(d2);
        }
#pragma unroll
        for (int u = 0; u < 8; ++u) {
            unsigned bin = orf[u] >> ORD_SHIFT;
            if (bin <= uB) {                       // rare (<~40/4096 per warp)
                int i = o + u * 32 + lane;
                if (bin < uB) {
                    int p_ = atomicAdd(&scnt[w], 1);
                    dst[p_] = i;
                } else {
                    int p_ = atomicAdd(&bcnt[w], 1);
                    if (p_ < 128)
                        blist[w][p_] = (((ull)orf[u]) << 32) | (unsigned)i;
                }
            }
        }
    }
    __syncwarp();

    const int outn = scnt[w];       // == below
    const int brun = bcnt[w];
    const int r = KNN - outn;

    if (brun <= 128) {
        // warp-cooperative selection of r smallest (key,idx) from the list
        ull e[4];
#pragma unroll
        for (int t_ = 0; t_ < 4; ++t_) {
            int id = t_ * 32 + lane;
            e[t_] = (id < brun) ? blist[w][id] : ~0ull;
        }
        for (int s_ = 0; s_ < r; ++s_) {
            ull lm = e[0];
            lm = e[1] < lm ? e[1] : lm;
            lm = e[2] < lm ? e[2] : lm;
            lm = e[3] < lm ? e[3] : lm;
            ull wm = lm;
#pragma unroll
            for (int d_ = 16; d_ > 0; d_ >>= 1) {
                ull o = __shfl_xor_sync(0xffffffffu, wm, d_);
                wm = o < wm ? o : wm;
            }
            if (lane == 0) dst[outn + s_] = (int)(wm & 0xffffffffu);
#pragma unroll
            for (int t_ = 0; t_ < 4; ++t_)
                if (e[t_] == wm) e[t_] = ~0ull;
        }
    } else {
        // cold fallback (pathological tie density): repeated warp-min rescans
        ull last = 0ull;
        for (int s_ = 0; s_ < r; ++s_) {
            ull best = ~0ull;
            for (int i = lane; i < Npts; i += 32) {
                float4 p = sp[i];
                float d2 = fmaf(-2.0f, fmaf(qx, p.x, fmaf(qy, p.y, qz * p.z)), qn + p.w);
                unsigned orf_ = ordflt(d2);
                if ((int)(orf_ >> ORD_SHIFT) == B) {
                    ull key = (((ull)orf_) << 32) | (unsigned)i;
                    if (key > last && key < best) best = key;
                }
            }
#pragma unroll
            for (int d_ = 16; d_ > 0; d_ >>= 1) {
                ull o = __shfl_xor_sync(0xffffffffu, best, d_);
                best = o < best ? o : best;
            }
            if (lane == 0) dst[outn + s_] = (int)(best & 0xffffffffu);
            last = best;
        }
    }
}

// ---------------------------------------------------------------------------
// Precompute kernel: g_h1pre[n][j] = feat[n] @ W1[3:67] + b1   (pre-relu)
// Plain register-tiled GEMM, 128 rows/block, thread tile 4x8 with f32x2.
// ---------------------------------------------------------------------------
#define PRE_TPB 256

__global__ void __launch_bounds__(PRE_TPB)
pre_kernel(const float* __restrict__ feat,
           const float* __restrict__ W1,
           const float* __restrict__ b1)
{
    __shared__ __align__(16) float fT[CIN * 128];   // featT[c][row]  32 KB
    __shared__ __align__(16) float Wf[CIN * H1];    // W1 rows 3..66  16 KB

    const int t  = threadIdx.x;
    const int n0 = blockIdx.x * 128;

    // stage Wf: Wf[i] = W1[192 + i] (rows 3..66, linear)
    for (int i = t; i < CIN * H1 / 4; i += PRE_TPB)
        ((float4*)Wf)[i] = *(const float4*)(W1 + 192 + i * 4);

    // stage feat transposed
    {
        const int row  = t >> 1;
        const int half = t & 1;
        const float4* f4 = (const float4*)(feat + (size_t)(n0 + row) * CIN);
#pragma unroll
        for (int r_ = 0; r_ < 8; ++r_) {
            float4 v = f4[half * 8 + r_];
            int c0 = half * 32 + r_ * 4;
            fT[(c0 + 0) * 128 + row] = v.x;
            fT[(c0 + 1) * 128 + row] = v.y;
            fT[(c0 + 2) * 128 + row] = v.z;
            fT[(c0 + 3) * 128 + row] = v.w;
        }
    }
    __syncthreads();

    const int tk = t & 31;
    const int tj = t >> 5;

    ull acc[4][4];
    {
        float4 bA = ((const float4*)b1)[tj * 2];
        float4 bB = ((const float4*)b1)[tj * 2 + 1];
        ull bp[4] = { pack2(bA.x, bA.y), pack2(bA.z, bA.w),
                      pack2(bB.x, bB.y), pack2(bB.z, bB.w) };
#pragma unroll
        for (int r_ = 0; r_ < 4; ++r_)
#pragma unroll
            for (int p_ = 0; p_ < 4; ++p_) acc[r_][p_] = bp[p_];
    }

    for (int c = 0; c < CIN; ++c) {
        float4 xv = *(const float4*)&fT[c * 128 + tk * 4];
        ulonglong2 wA = *(const ulonglong2*)&Wf[c * H1 + tj * 8];
        ulonglong2 wB = *(const ulonglong2*)&Wf[c * H1 + tj * 8 + 4];
        ull x0 = pack2(xv.x, xv.x);
        ull x1 = pack2(xv.y, xv.y);
        ull x2 = pack2(xv.z, xv.z);
        ull x3 = pack2(xv.w, xv.w);
        acc[0][0] = fma2(x0, wA.x, acc[0][0]);
        acc[0][1] = fma2(x0, wA.y, acc[0][1]);
        acc[0][2] = fma2(x0, wB.x, acc[0][2]);
        acc[0][3] = fma2(x0, wB.y, acc[0][3]);
        acc[1][0] = fma2(x1, wA.x, acc[1][0]);
        acc[1][1] = fma2(x1, wA.y, acc[1][1]);
        acc[1][2] = fma2(x1, wB.x, acc[1][2]);
        acc[1][3] = fma2(x1, wB.y, acc[1][3]);
        acc[2][0] = fma2(x2, wA.x, acc[2][0]);
        acc[2][1] = fma2(x2, wA.y, acc[2][1]);
        acc[2][2] = fma2(x2, wB.x, acc[2][2]);
        acc[2][3] = fma2(x2, wB.y, acc[2][3]);
        acc[3][0] = fma2(x3, wA.x, acc[3][0]);
        acc[3][1] = fma2(x3, wA.y, acc[3][1]);
        acc[3][2] = fma2(x3, wB.x, acc[3][2]);
        acc[3][3] = fma2(x3, wB.y, acc[3][3]);
    }

#pragma unroll
    for (int r_ = 0; r_ < 4; ++r_)
#pragma unroll
        for (int p_ = 0; p_ < 4; ++p_)
            *(ull*)&g_h1pre[(size_t)(n0 + tk * 4 + r_) * H1 + tj * 8 + p_ * 2]
                = acc[r_][p_];
}

// ---------------------------------------------------------------------------
// MLP v3: gather precomputed h1_pre + xyz correction + relu, then phase-2
// register-tiled GEMM [128x64]@[64x128] with f32x2, max-pool epilogue.
// ---------------------------------------------------------------------------
#define MQPB    4
#define MLP_TPB 256

__global__ void __launch_bounds__(MLP_TPB, 2)
mlp_kernel(const float* __restrict__ pos,
           const float* __restrict__ W1,
           const float* __restrict__ W2,
           const float* __restrict__ b2,
           const void*  __restrict__ idxp,
           float* __restrict__ outp)
{
    __shared__ __align__(16) float W2s[H1 * H2];    // 32 KB
    __shared__ __align__(16) float h1T[H1 * 128];   // 32 KB; later redscr[32][129]
    __shared__ __align__(16) float W1x[3 * H1];     // xyz rows of W1

    const int t  = threadIdx.x;
    const int q0 = blockIdx.x * MQPB;
    const int b  = q0 >> 10;

    // ---- stage weights ----
    for (int i = t; i < H1 * H2 / 4; i += MLP_TPB)
        ((float4*)W2s)[i] = ((const float4*)W2)[i];
    if (t < 48) ((float4*)W1x)[t] = ((const float4*)W1)[t];
    __syncthreads();   // gather below reads W1x from smem

    // ---- gather h1_pre rows + xyz correction + relu, transposed store ----
    {
        const int row  = t >> 1;        // 0..127
        const int half = t & 1;
        const int lq   = row >> 5;
        const int k    = row & 31;
        const int q    = q0 + lq;

        const float* posb = pos + (size_t)b * Npts * 3;
        const int is64 = idx_is64(idxp);
        const long long qi = load_idx2(idxp, q, is64);
        const int n = g_nn[(size_t)q * KNN + k];

        const float x0 = posb[n * 3 + 0] - posb[qi * 3 + 0];
        const float x1 = posb[n * 3 + 1] - posb[qi * 3 + 1];
        const float x2 = posb[n * 3 + 2] - posb[qi * 3 + 2];

        const float4* pre4 = (const float4*)(g_h1pre + (size_t)((b << 12) + n) * H1);
#pragma unroll
        for (int r_ = 0; r_ < 8; ++r_) {
            float4 v = pre4[half * 8 + r_];
            int j0 = half * 32 + r_ * 4;
            float4 wx = *(const float4*)&W1x[j0];
            float4 wy = *(const float4*)&W1x[H1 + j0];
            float4 wz = *(const float4*)&W1x[2 * H1 + j0];
            v.x = fmaxf(fmaf(x0, wx.x, fmaf(x1, wy.x, fmaf(x2, wz.x, v.x))), 0.0f);
            v.y = fmaxf(fmaf(x0, wx.y, fmaf(x1, wy.y, fmaf(x2, wz.y, v.y))), 0.0f);
            v.z = fmaxf(fmaf(x0, wx.z, fmaf(x1, wy.z, fmaf(x2, wz.z, v.z))), 0.0f);
            v.w = fmaxf(fmaf(x0, wx.w, fmaf(x1, wy.w, fmaf(x2, wz.w, v.w))), 0.0f);
            h1T[(j0 + 0) * 128 + row] = v.x;
            h1T[(j0 + 1) * 128 + row] = v.y;
            h1T[(j0 + 2) * 128 + row] = v.z;
            h1T[(j0 + 3) * 128 + row] = v.w;
        }
    }
    __syncthreads();

    // ---- phase 2: tile 4 rows (tk) x 16 cols (td), f32x2 over d-pairs ----
    const int tk = t & 31;
    const int td = t >> 5;
    ull acc2[4][8];
#pragma unroll
    for (int r_ = 0; r_ < 4; ++r_)
#pragma unroll
        for (int p_ = 0; p_ < 8; ++p_) acc2[r_][p_] = 0ull;

    for (int j = 0; j < H1; ++j) {
        float4 hv = *(const float4*)&h1T[j * 128 + tk * 4];
        const ulonglong2* wp = (const ulonglong2*)&W2s[j * H2 + td * 16];
        ulonglong2 wA = wp[0], wB = wp[1], wC = wp[2], wD = wp[3];
        ull h0 = pack2(hv.x, hv.x);
        ull h1v = pack2(hv.y, hv.y);
        ull h2 = pack2(hv.z, hv.z);
        ull h3 = pack2(hv.w, hv.w);
        acc2[0][0] = fma2(h0, wA.x, acc2[0][0]);
        acc2[0][1] = fma2(h0, wA.y, acc2[0][1]);
        acc2[0][2] = fma2(h0, wB.x, acc2[0][2]);
        acc2[0][3] = fma2(h0, wB.y, acc2[0][3]);
        acc2[0][4] = fma2(h0, wC.x, acc2[0][4]);
        acc2[0][5] = fma2(h0, wC.y, acc2[0][5]);
        acc2[0][6] = fma2(h0, wD.x, acc2[0][6]);
        acc2[0][7] = fma2(h0, wD.y, acc2[0][7]);
        acc2[1][0] = fma2(h1v, wA.x, acc2[1][0]);
        acc2[1][1] = fma2(h1v, wA.y, acc2[1][1]);
        acc2[1][2] = fma2(h1v, wB.x, acc2[1][2]);
        acc2[1][3] = fma2(h1v, wB.y, acc2[1][3]);
        acc2[1][4] = fma2(h1v, wC.x, acc2[1][4]);
        acc2[1][5] = fma2(h1v, wC.y, acc2[1][5]);
        acc2[1][6] = fma2(h1v, wD.x, acc2[1][6]);
        acc2[1][7] = fma2(h1v, wD.y, acc2[1][7]);
        acc2[2][0] = fma2(h2, wA.x, acc2[2][0]);
        acc2[2][1] = fma2(h2, wA.y, acc2[2][1]);
        acc2[2][2] = fma2(h2, wB.x, acc2[2][2]);
        acc2[2][3] = fma2(h2, wB.y, acc2[2][3]);
        acc2[2][4] = fma2(h2, wC.x, acc2[2][4]);
        acc2[2][5] = fma2(h2, wC.y, acc2[2][5]);
        acc2[2][6] = fma2(h2, wD.x, acc2[2][6]);
        acc2[2][7] = fma2(h2, wD.y, acc2[2][7]);
        acc2[3][0] = fma2(h3, wA.x, acc2[3][0]);
        acc2[3][1] = fma2(h3, wA.y, acc2[3][1]);
        acc2[3][2] = fma2(h3, wB.x, acc2[3][2]);
        acc2[3][3] = fma2(h3, wB.y, acc2[3][3]);
        acc2[3][4] = fma2(h3, wC.x, acc2[3][4]);
        acc2[3][5] = fma2(h3, wC.y, acc2[3][5]);
        acc2[3][6] = fma2(h3, wD.x, acc2[3][6]);
        acc2[3][7] = fma2(h3, wD.y, acc2[3][7]);
    }
    __syncthreads();   // h1T reads done; reuse as reduction scratch

    // ---- epilogue: per-thread max over 4 rows, scratch, final reduce ----
    float* redscr = h1T;   // [32][129]
#pragma unroll
    for (int p_ = 0; p_ < 8; ++p_) {
        float e0, o0, e1, o1, e2, o2, e3, o3;
        unpack2(acc2[0][p_], e0, o0);
        unpack2(acc2[1][p_], e1, o1);
        unpack2(acc2[2][p_], e2, o2);
        unpack2(acc2[3][p_], e3, o3);
        float me = fmaxf(fmaxf(e0, e1), fmaxf(e2, e3));
        float mo = fmaxf(fmaxf(o0, o1), fmaxf(o2, o3));
        redscr[tk * 129 + td * 16 + p_ * 2 + 0] = me;
        redscr[tk * 129 + td * 16 + p_ * 2 + 1] = mo;
    }
    __syncthreads();

    for (int o = t; o < MQPB * H2; o += MLP_TPB) {
        int lq = o >> 7;
        int d  = o & 127;
        float mx = -FLT_MAX;
#pragma unroll
        for (int s_ = 0; s_ < 8; ++s_)
            mx = fmaxf(mx, redscr[(lq * 8 + s_) * 129 + d]);
        outp[(size_t)(q0 + lq) * H2 + d] = fmaxf(mx + b2[d], 0.0f);
    }
}

// ---------------------------------------------------------------------------
// launcher — knn FIRST so the ncu capture slot (which landed on the first
// launch of the replay group in R8/R9) profiles knn_kernel this time.
// knn and pre are independent; mlp depends on both.
// ---------------------------------------------------------------------------
extern "C" void kernel_launch(void* const* d_in, const int* in_sizes, int n_in,
                              void* d_out, int out_size)
{
    const float* pos  = (const float*)d_in[0];   // [16,4096,3]
    const float* feat = (const float*)d_in[1];   // [16,4096,64]
    const float* W1   = (const float*)d_in[2];   // [67,64]
    const float* b1   = (const float*)d_in[3];   // [64]
    const float* W2   = (const float*)d_in[4];   // [64,128]
    const float* b2   = (const float*)d_in[5];   // [128]
    const void*  idxp = d_in[6];                 // [16,1024] int64 or int32

    float* out_posq = (float*)d_out;                          // 16*1024*3
    float* out_feat = (float*)d_out + (size_t)Bdim * Mq * 3;  // 16*1024*128

    knn_kernel<<<Bdim * (Mq / KQPB), KTPB>>>(pos, idxp, out_posq);

    pre_kernel<<<(Bdim * Npts) / 128, PRE_TPB>>>(feat, W1, b1);

    mlp_kernel<<<(Bdim * Mq) / MQPB, MLP_TPB>>>(pos, W1, W2, b2, idxp, out_feat);
}

// round 13
// speedup vs baseline: 1.3787x; 1.0148x over previous
#include <cuda_runtime.h>
#include <float.h>

#define Bdim 16
#define Npts 4096
#define Mq   1024
#define CIN  64
#define KNN  32
#define CH   (CIN + 3)   // 67 input channels (rel xyz + features)
#define H1   64
#define H2   128

// scratch: neighbor indices + precomputed feature part of layer 1
__device__ int   g_nn[Bdim * Mq * KNN];
__device__ float g_h1pre[Bdim * Npts * H1];   // feat @ W1[3:] + b1 (pre-relu)

typedef unsigned long long ull;

// ---------------------------------------------------------------------------
// helpers
// ---------------------------------------------------------------------------
__device__ __forceinline__ ull pack2(float lo, float hi) {
    ull r;
    asm("mov.b64 %0, {%1, %2};" : "=l"(r) : "f"(lo), "f"(hi));
    return r;
}
__device__ __forceinline__ void unpack2(ull v, float& lo, float& hi) {
    asm("mov.b64 {%0, %1}, %2;" : "=f"(lo), "=f"(hi) : "l"(v));
}
__device__ __forceinline__ ull fma2(ull a, ull b, ull c) {
    ull r;
    asm("fma.rn.f32x2 %0, %1, %2, %3;" : "=l"(r) : "l"(a), "l"(b), "l"(c));
    return r;
}

// idx dtype detection: int64 values < 4096 -> all odd 32-bit words are 0.
__device__ __forceinline__ int idx_is64(const void* idxp) {
    const int* p = (const int*)idxp;
    int acc = p[1] | p[3] | p[5] | p[7] | p[9] | p[11] | p[13] | p[15];
    return acc == 0;
}
__device__ __forceinline__ long long load_idx2(const void* idxp, int i, int is64) {
    return is64 ? ((const long long*)idxp)[i] : (long long)((const int*)idxp)[i];
}

// ordered-float transform: total order on float bits as unsigned
__device__ __forceinline__ unsigned ordflt(float f) {
    unsigned fb = __float_as_uint(f);
    return fb ^ ((unsigned)((int)fb >> 31) | 0x80000000u);
}

// ---------------------------------------------------------------------------
// KNN kernel v7: identical algorithm to v6 (R12, 532.6us baseline) but with
// smem cut to ~104 KB so TWO blocks fit per SM (8 warps/SMSP instead of 4):
//   - u8 SATURATING histogram counters (lossless for radix select: the
//     boundary scan only consumes counts while cum+c < K=32, so every count
//     it relies on is exact; saturated bins (>=255>=32) hit the identical
//     boundary decision).
//   - boundary list 128 -> 64 entries (typical population ~4-10; overflow
//     handled by the exact rescan fallback).
// No launch_bounds min-blocks clause: regs are naturally ~54, so 2 blocks
// arrive without forcing ptxas (R9's spill failure mode avoided).
// ---------------------------------------------------------------------------
#define KQPB      16     // queries (warps) per block
#define KTPB      512
#define NBIN      2048
#define ORD_SHIFT 21     // 32 - log2(NBIN)
#define BLMAX     64

__global__ void __launch_bounds__(KTPB)
knn_kernel(const float* __restrict__ pos,
           const void*  __restrict__ idxp,
           float* __restrict__ out_posq)
{
    __shared__ __align__(16) float4 sp[Npts];                // 64 KB
    __shared__ __align__(16) unsigned char hist[KQPB][NBIN]; // 32 KB
    __shared__ __align__(16) ull blist[KQPB][BLMAX];         // 8 KB
    __shared__ int scnt[KQPB], bcnt[KQPB];

    const int tid  = threadIdx.x;
    const int w    = tid >> 5;
    const int lane = tid & 31;
    const unsigned lt = (1u << lane) - 1u;
    const int b    = blockIdx.x >> 6;                 // 64 blocks per batch
    const int m    = ((blockIdx.x & 63) << 4) | w;
    const int q    = (b << 10) | m;

    const float* posb = pos + b * Npts * 3;

    // zero this warp's histogram (2 KB -> 4 uint4 stores per lane)
    {
        uint4* hz = (uint4*)hist[w];
        uint4 z = make_uint4(0, 0, 0, 0);
#pragma unroll
        for (int i = lane; i < NBIN / 16; i += 32) hz[i] = z;
    }
    if (lane == 0) { scnt[w] = 0; bcnt[w] = 0; }

    // stage the full point tile once
    for (int i = tid; i < Npts; i += KTPB) {
        float px = posb[i * 3 + 0];
        float py = posb[i * 3 + 1];
        float pz = posb[i * 3 + 2];
        sp[i] = make_float4(px, py, pz, px * px + py * py + pz * pz);
    }

    const int is64 = idx_is64(idxp);
    const long long qi = load_idx2(idxp, q, is64);
    const float qx = posb[qi * 3 + 0];
    const float qy = posb[qi * 3 + 1];
    const float qz = posb[qi * 3 + 2];
    const float qn = qx * qx + qy * qy + qz * qz;

    if (lane == 0) {
        out_posq[q * 3 + 0] = qx;
        out_posq[q * 3 + 1] = qy;
        out_posq[q * 3 + 2] = qz;
    }
    __syncthreads();

    // ---------------- pass 1: histogram (8x ILP, u8 saturating) ----------
    for (int o = 0; o < Npts; o += 256) {
        unsigned bin[8];
#pragma unroll
        for (int u = 0; u < 8; ++u) {
            float4 p = sp[o + u * 32 + lane];
            float d2 = fmaf(-2.0f, fmaf(qx, p.x, fmaf(qy, p.y, qz * p.z)), qn + p.w);
            bin[u] = ordflt(d2) >> ORD_SHIFT;
        }
#pragma unroll
        for (int u = 0; u < 8; ++u) {
            unsigned mm = __match_any_sync(0xffffffffu, bin[u]);
            if ((mm & lt) == 0) {  // lowest lane of each equal-bin group
                int v = (int)hist[w][bin[u]] + __popc(mm);
                hist[w][bin[u]] = (unsigned char)(v > 255 ? 255 : v);
            }
        }
    }
    __syncwarp();

    // ---------------- boundary-bin search ----------------
    int B = 0; unsigned below = 0;
    {
        const int base = lane * (NBIN / 32);
        unsigned s = 0;
#pragma unroll 8
        for (int j = 0; j < NBIN / 32; ++j) s += hist[w][base + j];
        unsigned incl = s;
#pragma unroll
        for (int d_ = 1; d_ < 32; d_ <<= 1) {
            unsigned t_ = __shfl_up_sync(0xffffffffu, incl, d_);
            if (lane >= d_) incl += t_;
        }
        unsigned excl = incl - s;
        unsigned bal = __ballot_sync(0xffffffffu, incl >= (unsigned)KNN);
        int L = __ffs(bal) - 1;
        if (lane == L) {
            unsigned cum = excl;
            for (int j = 0; j < NBIN / 32; ++j) {
                unsigned c = hist[w][base + j];
                if (cum + c >= (unsigned)KNN) { B = base + j; below = cum; break; }
                cum += c;
            }
        }
        B = __shfl_sync(0xffffffffu, B, L);
        below = __shfl_sync(0xffffffffu, below, L);
    }

    // ---------------- pass 2: collect (8x ILP, rare-path atomics) ----------
    int* dst = g_nn + q * KNN;
    const unsigned uB = (unsigned)B;

    for (int o = 0; o < Npts; o += 256) {
        unsigned orf[8];
#pragma unroll
        for (int u = 0; u < 8; ++u) {
            float4 p = sp[o + u * 32 + lane];
            float d2 = fmaf(-2.0f, fmaf(qx, p.x, fmaf(qy, p.y, qz * p.z)), qn + p.w);
            orf[u] = ordflt(d2);
        }
#pragma unroll
        for (int u = 0; u < 8; ++u) {
            unsigned bin = orf[u] >> ORD_SHIFT;
            if (bin <= uB) {                       // rare (<~40/4096 per warp)
                int i = o + u * 32 + lane;
                if (bin < uB) {
                    int p_ = atomicAdd(&scnt[w], 1);
                    dst[p_] = i;
                } else {
                    int p_ = atomicAdd(&bcnt[w], 1);
                    if (p_ < BLMAX)
                        blist[w][p_] = (((ull)orf[u]) << 32) | (unsigned)i;
                }
            }
        }
    }
    __syncwarp();

    const int outn = scnt[w];       // == below
    const int brun = bcnt[w];
    const int r = KNN - outn;

    if (brun <= BLMAX) {
        // warp-cooperative selection of r smallest (key,idx) from the list
        ull e[2];
#pragma unroll
        for (int t_ = 0; t_ < 2; ++t_) {
            int id = t_ * 32 + lane;
            e[t_] = (id < brun) ? blist[w][id] : ~0ull;
        }
        for (int s_ = 0; s_ < r; ++s_) {
            ull wm = e[0] < e[1] ? e[0] : e[1];
#pragma unroll
            for (int d_ = 16; d_ > 0; d_ >>= 1) {
                ull o = __shfl_xor_sync(0xffffffffu, wm, d_);
                wm = o < wm ? o : wm;
            }
            if (lane == 0) dst[outn + s_] = (int)(wm & 0xffffffffu);
#pragma unroll
            for (int t_ = 0; t_ < 2; ++t_)
                if (e[t_] == wm) e[t_] = ~0ull;
        }
    } else {
        // cold fallback (pathological tie density): repeated warp-min rescans
        ull last = 0ull;
        for (int s_ = 0; s_ < r; ++s_) {
            ull best = ~0ull;
            for (int i = lane; i < Npts; i += 32) {
                float4 p = sp[i];
                float d2 = fmaf(-2.0f, fmaf(qx, p.x, fmaf(qy, p.y, qz * p.z)), qn + p.w);
                unsigned orf_ = ordflt(d2);
                if ((int)(orf_ >> ORD_SHIFT) == B) {
                    ull key = (((ull)orf_) << 32) | (unsigned)i;
                    if (key > last && key < best) best = key;
                }
            }
#pragma unroll
            for (int d_ = 16; d_ > 0; d_ >>= 1) {
                ull o = __shfl_xor_sync(0xffffffffu, best, d_);
                best = o < best ? o : best;
            }
            if (lane == 0) dst[outn + s_] = (int)(best & 0xffffffffu);
            last = best;
        }
    }
}

// ---------------------------------------------------------------------------
// Precompute kernel: g_h1pre[n][j] = feat[n] @ W1[3:67] + b1   (pre-relu)
// Plain register-tiled GEMM, 128 rows/block, thread tile 4x8 with f32x2.
// ---------------------------------------------------------------------------
#define PRE_TPB 256

__global__ void __launch_bounds__(PRE_TPB)
pre_kernel(const float* __restrict__ feat,
           const float* __restrict__ W1,
           const float* __restrict__ b1)
{
    __shared__ __align__(16) float fT[CIN * 128];   // featT[c][row]  32 KB
    __shared__ __align__(16) float Wf[CIN * H1];    // W1 rows 3..66  16 KB

    const int t  = threadIdx.x;
    const int n0 = blockIdx.x * 128;

    // stage Wf: Wf[i] = W1[192 + i] (rows 3..66, linear)
    for (int i = t; i < CIN * H1 / 4; i += PRE_TPB)
        ((float4*)Wf)[i] = *(const float4*)(W1 + 192 + i * 4);

    // stage feat transposed
    {
        const int row  = t >> 1;
        const int half = t & 1;
        const float4* f4 = (const float4*)(feat + (size_t)(n0 + row) * CIN);
#pragma unroll
        for (int r_ = 0; r_ < 8; ++r_) {
            float4 v = f4[half * 8 + r_];
            int c0 = half * 32 + r_ * 4;
            fT[(c0 + 0) * 128 + row] = v.x;
            fT[(c0 + 1) * 128 + row] = v.y;
            fT[(c0 + 2) * 128 + row] = v.z;
            fT[(c0 + 3) * 128 + row] = v.w;
        }
    }
    __syncthreads();

    const int tk = t & 31;
    const int tj = t >> 5;

    ull acc[4][4];
    {
        float4 bA = ((const float4*)b1)[tj * 2];
        float4 bB = ((const float4*)b1)[tj * 2 + 1];
        ull bp[4] = { pack2(bA.x, bA.y), pack2(bA.z, bA.w),
                      pack2(bB.x, bB.y), pack2(bB.z, bB.w) };
#pragma unroll
        for (int r_ = 0; r_ < 4; ++r_)
#pragma unroll
            for (int p_ = 0; p_ < 4; ++p_) acc[r_][p_] = bp[p_];
    }

    for (int c = 0; c < CIN; ++c) {
        float4 xv = *(const float4*)&fT[c * 128 + tk * 4];
        ulonglong2 wA = *(const ulonglong2*)&Wf[c * H1 + tj * 8];
        ulonglong2 wB = *(const ulonglong2*)&Wf[c * H1 + tj * 8 + 4];
        ull x0 = pack2(xv.x, xv.x);
        ull x1 = pack2(xv.y, xv.y);
        ull x2 = pack2(xv.z, xv.z);
        ull x3 = pack2(xv.w, xv.w);
        acc[0][0] = fma2(x0, wA.x, acc[0][0]);
        acc[0][1] = fma2(x0, wA.y, acc[0][1]);
        acc[0][2] = fma2(x0, wB.x, acc[0][2]);
        acc[0][3] = fma2(x0, wB.y, acc[0][3]);
        acc[1][0] = fma2(x1, wA.x, acc[1][0]);
        acc[1][1] = fma2(x1, wA.y, acc[1][1]);
        acc[1][2] = fma2(x1, wB.x, acc[1][2]);
        acc[1][3] = fma2(x1, wB.y, acc[1][3]);
        acc[2][0] = fma2(x2, wA.x, acc[2][0]);
        acc[2][1] = fma2(x2, wA.y, acc[2][1]);
        acc[2][2] = fma2(x2, wB.x, acc[2][2]);
        acc[2][3] = fma2(x2, wB.y, acc[2][3]);
        acc[3][0] = fma2(x3, wA.x, acc[3][0]);
        acc[3][1] = fma2(x3, wA.y, acc[3][1]);
        acc[3][2] = fma2(x3, wB.x, acc[3][2]);
        acc[3][3] = fma2(x3, wB.y, acc[3][3]);
    }

#pragma unroll
    for (int r_ = 0; r_ < 4; ++r_)
#pragma unroll
        for (int p_ = 0; p_ < 4; ++p_)
            *(ull*)&g_h1pre[(size_t)(n0 + tk * 4 + r_) * H1 + tj * 8 + p_ * 2]
                = acc[r_][p_];
}

// ---------------------------------------------------------------------------
// MLP v3: gather precomputed h1_pre + xyz correction + relu, then phase-2
// register-tiled GEMM [128x64]@[64x128] with f32x2, max-pool epilogue.
// ---------------------------------------------------------------------------
#define MQPB    4
#define MLP_TPB 256

__global__ void __launch_bounds__(MLP_TPB, 2)
mlp_kernel(const float* __restrict__ pos,
           const float* __restrict__ W1,
           const float* __restrict__ W2,
           const float* __restrict__ b2,
           const void*  __restrict__ idxp,
           float* __restrict__ outp)
{
    __shared__ __align__(16) float W2s[H1 * H2];    // 32 KB
    __shared__ __align__(16) float h1T[H1 * 128];   // 32 KB; later redscr[32][129]
    __shared__ __align__(16) float W1x[3 * H1];     // xyz rows of W1

    const int t  = threadIdx.x;
    const int q0 = blockIdx.x * MQPB;
    const int b  = q0 >> 10;

    // ---- stage weights ----
    for (int i = t; i < H1 * H2 / 4; i += MLP_TPB)
        ((float4*)W2s)[i] = ((const float4*)W2)[i];
    if (t < 48) ((float4*)W1x)[t] = ((const float4*)W1)[t];
    __syncthreads();   // gather below reads W1x from smem

    // ---- gather h1_pre rows + xyz correction + relu, transposed store ----
    {
        const int row  = t >> 1;        // 0..127
        const int half = t & 1;
        const int lq   = row >> 5;
        const int k    = row & 31;
        const int q    = q0 + lq;

        const float* posb = pos + (size_t)b * Npts * 3;
        const int is64 = idx_is64(idxp);
        const long long qi = load_idx2(idxp, q, is64);
        const int n = g_nn[(size_t)q * KNN + k];

        const float x0 = posb[n * 3 + 0] - posb[qi * 3 + 0];
        const float x1 = posb[n * 3 + 1] - posb[qi * 3 + 1];
        const float x2 = posb[n * 3 + 2] - posb[qi * 3 + 2];

        const float4* pre4 = (const float4*)(g_h1pre + (size_t)((b << 12) + n) * H1);
#pragma unroll
        for (int r_ = 0; r_ < 8; ++r_) {
            float4 v = pre4[half * 8 + r_];
            int j0 = half * 32 + r_ * 4;
            float4 wx = *(const float4*)&W1x[j0];
            float4 wy = *(const float4*)&W1x[H1 + j0];
            float4 wz = *(const float4*)&W1x[2 * H1 + j0];
            v.x = fmaxf(fmaf(x0, wx.x, fmaf(x1, wy.x, fmaf(x2, wz.x, v.x))), 0.0f);
            v.y = fmaxf(fmaf(x0, wx.y, fmaf(x1, wy.y, fmaf(x2, wz.y, v.y))), 0.0f);
            v.z = fmaxf(fmaf(x0, wx.z, fmaf(x1, wy.z, fmaf(x2, wz.z, v.z))), 0.0f);
            v.w = fmaxf(fmaf(x0, wx.w, fmaf(x1, wy.w, fmaf(x2, wz.w, v.w))), 0.0f);
            h1T[(j0 + 0) * 128 + row] = v.x;
            h1T[(j0 + 1) * 128 + row] = v.y;
            h1T[(j0 + 2) * 128 + row] = v.z;
            h1T[(j0 + 3) * 128 + row] = v.w;
        }
    }
    __syncthreads();

    // ---- phase 2: tile 4 rows (tk) x 16 cols (td), f32x2 over d-pairs ----
    const int tk = t & 31;
    const int td = t >> 5;
    ull acc2[4][8];
#pragma unroll
    for (int r_ = 0; r_ < 4; ++r_)
#pragma unroll
        for (int p_ = 0; p_ < 8; ++p_) acc2[r_][p_] = 0ull;

    for (int j = 0; j < H1; ++j) {
        float4 hv = *(const float4*)&h1T[j * 128 + tk * 4];
        const ulonglong2* wp = (const ulonglong2*)&W2s[j * H2 + td * 16];
        ulonglong2 wA = wp[0], wB = wp[1], wC = wp[2], wD = wp[3];
        ull h0 = pack2(hv.x, hv.x);
        ull h1v = pack2(hv.y, hv.y);
        ull h2 = pack2(hv.z, hv.z);
        ull h3 = pack2(hv.w, hv.w);
        acc2[0][0] = fma2(h0, wA.x, acc2[0][0]);
        acc2[0][1] = fma2(h0, wA.y, acc2[0][1]);
        acc2[0][2] = fma2(h0, wB.x, acc2[0][2]);
        acc2[0][3] = fma2(h0, wB.y, acc2[0][3]);
        acc2[0][4] = fma2(h0, wC.x, acc2[0][4]);
        acc2[0][5] = fma2(h0, wC.y, acc2[0][5]);
        acc2[0][6] = fma2(h0, wD.x, acc2[0][6]);
        acc2[0][7] = fma2(h0, wD.y, acc2[0][7]);
        acc2[1][0] = fma2(h1v, wA.x, acc2[1][0]);
        acc2[1][1] = fma2(h1v, wA.y, acc2[1][1]);
        acc2[1][2] = fma2(h1v, wB.x, acc2[1][2]);
        acc2[1][3] = fma2(h1v, wB.y, acc2[1][3]);
        acc2[1][4] = fma2(h1v, wC.x, acc2[1][4]);
        acc2[1][5] = fma2(h1v, wC.y, acc2[1][5]);
        acc2[1][6] = fma2(h1v, wD.x, acc2[1][6]);
        acc2[1][7] = fma2(h1v, wD.y, acc2[1][7]);
        acc2[2][0] = fma2(h2, wA.x, acc2[2][0]);
        acc2[2][1] = fma2(h2, wA.y, acc2[2][1]);
        acc2[2][2] = fma2(h2, wB.x, acc2[2][2]);
        acc2[2][3] = fma2(h2, wB.y, acc2[2][3]);
        acc2[2][4] = fma2(h2, wC.x, acc2[2][4]);
        acc2[2][5] = fma2(h2, wC.y, acc2[2][5]);
        acc2[2][6] = fma2(h2, wD.x, acc2[2][6]);
        acc2[2][7] = fma2(h2, wD.y, acc2[2][7]);
        acc2[3][0] = fma2(h3, wA.x, acc2[3][0]);
        acc2[3][1] = fma2(h3, wA.y, acc2[3][1]);
        acc2[3][2] = fma2(h3, wB.x, acc2[3][2]);
        acc2[3][3] = fma2(h3, wB.y, acc2[3][3]);
        acc2[3][4] = fma2(h3, wC.x, acc2[3][4]);
        acc2[3][5] = fma2(h3, wC.y, acc2[3][5]);
        acc2[3][6] = fma2(h3, wD.x, acc2[3][6]);
        acc2[3][7] = fma2(h3, wD.y, acc2[3][7]);
    }
    __syncthreads();   // h1T reads done; reuse as reduction scratch

    // ---- epilogue: per-thread max over 4 rows, scratch, final reduce ----
    float* redscr = h1T;   // [32][129]
#pragma unroll
    for (int p_ = 0; p_ < 8; ++p_) {
        float e0, o0, e1, o1, e2, o2, e3, o3;
        unpack2(acc2[0][p_], e0, o0);
        unpack2(acc2[1][p_], e1, o1);
        unpack2(acc2[2][p_], e2, o2);
        unpack2(acc2[3][p_], e3, o3);
        float me = fmaxf(fmaxf(e0, e1), fmaxf(e2, e3));
        float mo = fmaxf(fmaxf(o0, o1), fmaxf(o2, o3));
        redscr[tk * 129 + td * 16 + p_ * 2 + 0] = me;
        redscr[tk * 129 + td * 16 + p_ * 2 + 1] = mo;
    }
    __syncthreads();

    for (int o = t; o < MQPB * H2; o += MLP_TPB) {
        int lq = o >> 7;
        int d  = o & 127;
        float mx = -FLT_MAX;
#pragma unroll
        for (int s_ = 0; s_ < 8; ++s_)
            mx = fmaxf(mx, redscr[(lq * 8 + s_) * 129 + d]);
        outp[(size_t)(q0 + lq) * H2 + d] = fmaxf(mx + b2[d], 0.0f);
    }
}

// ---------------------------------------------------------------------------
// launcher — knn first (ncu capture slot lands on it)
// ---------------------------------------------------------------------------
extern "C" void kernel_launch(void* const* d_in, const int* in_sizes, int n_in,
                              void* d_out, int out_size)
{
    const float* pos  = (const float*)d_in[0];   // [16,4096,3]
    const float* feat = (const float*)d_in[1];   // [16,4096,64]
    const float* W1   = (const float*)d_in[2];   // [67,64]
    const float* b1   = (const float*)d_in[3];   // [64]
    const float* W2   = (const float*)d_in[4];   // [64,128]
    const float* b2   = (const float*)d_in[5];   // [128]
    const void*  idxp = d_in[6];                 // [16,1024] int64 or int32

    float* out_posq = (float*)d_out;                          // 16*1024*3
    float* out_feat = (float*)d_out + (size_t)Bdim * Mq * 3;  // 16*1024*128

    knn_kernel<<<Bdim * (Mq / KQPB), KTPB>>>(pos, idxp, out_posq);

    pre_kernel<<<(Bdim * Npts) / 128, PRE_TPB>>>(feat, W1, b1);

    mlp_kernel<<<(Bdim * Mq) / MQPB, MLP_TPB>>>(pos, W1, W2, b2, idxp, out_feat);
}

// round 14
// speedup vs baseline: 1.9454x; 1.4111x over previous
#include <cuda_runtime.h>
#include <float.h>

#define Bdim 16
#define Npts 4096
#define Mq   1024
#define CIN  64
#define KNN  32
#define CH   (CIN + 3)   // 67 input channels (rel xyz + features)
#define H1   64
#define H2   128

// scratch: neighbor indices + precomputed feature part of layer 1
__device__ int   g_nn[Bdim * Mq * KNN];
__device__ float g_h1pre[Bdim * Npts * H1];   // feat @ W1[3:] + b1 (pre-relu)

typedef unsigned long long ull;

// ---------------------------------------------------------------------------
// helpers
// ---------------------------------------------------------------------------
__device__ __forceinline__ ull pack2(float lo, float hi) {
    ull r;
    asm("mov.b64 %0, {%1, %2};" : "=l"(r) : "f"(lo), "f"(hi));
    return r;
}
__device__ __forceinline__ void unpack2(ull v, float& lo, float& hi) {
    asm("mov.b64 {%0, %1}, %2;" : "=f"(lo), "=f"(hi) : "l"(v));
}
__device__ __forceinline__ ull fma2(ull a, ull b, ull c) {
    ull r;
    asm("fma.rn.f32x2 %0, %1, %2, %3;" : "=l"(r) : "l"(a), "l"(b), "l"(c));
    return r;
}

// idx dtype detection: int64 values < 4096 -> all odd 32-bit words are 0.
__device__ __forceinline__ int idx_is64(const void* idxp) {
    const int* p = (const int*)idxp;
    int acc = p[1] | p[3] | p[5] | p[7] | p[9] | p[11] | p[13] | p[15];
    return acc == 0;
}
__device__ __forceinline__ long long load_idx2(const void* idxp, int i, int is64) {
    return is64 ? ((const long long*)idxp)[i] : (long long)((const int*)idxp)[i];
}

// ordered-float transform: total order on float bits as unsigned
__device__ __forceinline__ unsigned ordflt(float f) {
    unsigned fb = __float_as_uint(f);
    return fb ^ ((unsigned)((int)fb >> 31) | 0x80000000u);
}

// ---------------------------------------------------------------------------
// KNN kernel v8: prefix-bound radix select.
//   1. u8 histogram over the FIRST 1024 candidates only -> boundary bin B_A
//      (its cumulative count >=32, so the true global top-32 all have
//      bin <= B_A: guaranteed superset bound).
//   2. One full scan collecting all candidates with bin <= B_A into a
//      per-warp list (E[count] ~ 140, cap 224, >4-sigma; overflow ->
//      exact fallback: complete the histogram and run the R12 path).
//   3. Re-histogram the small list -> exact global boundary B2/below2.
//   4. Final collect (bins < B2 -> dst, == B2 -> tiny boundary list) +
//      warp-min extraction tail (R12-proven).
// Heavy match/RMW rounds per warp drop 16 -> ~9; smem 108.3 KB keeps
// 2 blocks/SM. u8 saturation remains lossless (boundary scan only consumes
// counts while cum < 32).
// ---------------------------------------------------------------------------
#define KQPB      16     // queries (warps) per block
#define KTPB      512
#define NBIN      1024
#define ORD_SHIFT 22     // 32 - log2(NBIN)
#define LCAP      224    // collected-candidate list capacity per warp
#define BLMAX     64     // boundary sub-list capacity (aliases hist row)

// boundary scan over a 1024-bin u8 histogram row: smallest bin B with
// cumulative count >= KNN, and `below` = cumulative count of bins < B.
__device__ __forceinline__ void boundary_scan(const unsigned char* __restrict__ h,
                                              int lane, int& B, unsigned& below) {
    const int base = lane * (NBIN / 32);
    unsigned s = 0;
#pragma unroll 8
    for (int j = 0; j < NBIN / 32; ++j) s += h[base + j];
    unsigned incl = s;
#pragma unroll
    for (int d_ = 1; d_ < 32; d_ <<= 1) {
        unsigned t_ = __shfl_up_sync(0xffffffffu, incl, d_);
        if (lane >= d_) incl += t_;
    }
    unsigned excl = incl - s;
    unsigned bal = __ballot_sync(0xffffffffu, incl >= (unsigned)KNN);
    int L = __ffs(bal) - 1;
    int Bl = 0; unsigned bel = 0;
    if (lane == L) {
        unsigned cum = excl;
        for (int j = 0; j < NBIN / 32; ++j) {
            unsigned cc = h[base + j];
            if (cum + cc >= (unsigned)KNN) { Bl = base + j; bel = cum; break; }
            cum += cc;
        }
    }
    B = __shfl_sync(0xffffffffu, Bl, L);
    below = __shfl_sync(0xffffffffu, bel, L);
}

// histogram candidates [o0, o1) into this warp's u8 row (8x ILP, saturating)
__device__ __forceinline__ void hist_range(const float4* __restrict__ sp,
                                           unsigned char* __restrict__ hw,
                                           float qx, float qy, float qz, float qn,
                                           int lane, unsigned lt, int o0, int o1) {
    for (int o = o0; o < o1; o += 256) {
        unsigned bin[8];
#pragma unroll
        for (int u = 0; u < 8; ++u) {
            float4 p = sp[o + u * 32 + lane];
            float d2 = fmaf(-2.0f, fmaf(qx, p.x, fmaf(qy, p.y, qz * p.z)), qn + p.w);
            bin[u] = ordflt(d2) >> ORD_SHIFT;
        }
#pragma unroll
        for (int u = 0; u < 8; ++u) {
            unsigned mm = __match_any_sync(0xffffffffu, bin[u]);
            if ((mm & lt) == 0) {  // lowest lane of each equal-bin group
                int v = (int)hw[bin[u]] + __popc(mm);
                hw[bin[u]] = (unsigned char)(v > 255 ? 255 : v);
            }
        }
    }
}

__global__ void __launch_bounds__(KTPB)
knn_kernel(const float* __restrict__ pos,
           const void*  __restrict__ idxp,
           float* __restrict__ out_posq)
{
    __shared__ __align__(16) float4 sp[Npts];                // 64 KB
    __shared__ __align__(16) unsigned char hist[KQPB][NBIN]; // 16 KB
    __shared__ __align__(16) ull list[KQPB][LCAP];           // 28 KB
    __shared__ int scnt[KQPB], scnt2[KQPB], bcnt2[KQPB];

    const int tid  = threadIdx.x;
    const int w    = tid >> 5;
    const int lane = tid & 31;
    const unsigned lt = (1u << lane) - 1u;
    const int b    = blockIdx.x >> 6;                 // 64 blocks per batch
    const int m    = ((blockIdx.x & 63) << 4) | w;
    const int q    = (b << 10) | m;

    const float* posb = pos + b * Npts * 3;

    // zero this warp's histogram (1 KB -> 2 uint4 stores per lane)
    {
        uint4* hz = (uint4*)hist[w];
        uint4 z = make_uint4(0, 0, 0, 0);
#pragma unroll
        for (int i = lane; i < NBIN / 16; i += 32) hz[i] = z;
    }
    if (lane == 0) { scnt[w] = 0; scnt2[w] = 0; bcnt2[w] = 0; }

    // stage the full point tile once
    for (int i = tid; i < Npts; i += KTPB) {
        float px = posb[i * 3 + 0];
        float py = posb[i * 3 + 1];
        float pz = posb[i * 3 + 2];
        sp[i] = make_float4(px, py, pz, px * px + py * py + pz * pz);
    }

    const int is64 = idx_is64(idxp);
    const long long qi = load_idx2(idxp, q, is64);
    const float qx = posb[qi * 3 + 0];
    const float qy = posb[qi * 3 + 1];
    const float qz = posb[qi * 3 + 2];
    const float qn = qx * qx + qy * qy + qz * qz;

    if (lane == 0) {
        out_posq[q * 3 + 0] = qx;
        out_posq[q * 3 + 1] = qy;
        out_posq[q * 3 + 2] = qz;
    }
    __syncthreads();

    // ---------------- phase 1: prefix histogram (first 1024 cands) --------
    hist_range(sp, hist[w], qx, qy, qz, qn, lane, lt, 0, 1024);
    __syncwarp();

    int BA; unsigned belowA;
    boundary_scan(hist[w], lane, BA, belowA);   // belowA unused; BA = bound bin
    const unsigned uBA = (unsigned)BA;

    // ---------------- phase 2: full scan, collect bin <= BA ---------------
    for (int o = 0; o < Npts; o += 256) {
        unsigned orf[8];
#pragma unroll
        for (int u = 0; u < 8; ++u) {
            float4 p = sp[o + u * 32 + lane];
            float d2 = fmaf(-2.0f, fmaf(qx, p.x, fmaf(qy, p.y, qz * p.z)), qn + p.w);
            orf[u] = ordflt(d2);
        }
#pragma unroll
        for (int u = 0; u < 8; ++u) {
            if ((orf[u] >> ORD_SHIFT) <= uBA) {    // rare (~150/4096 per warp)
                int p_ = atomicAdd(&scnt[w], 1);
                if (p_ < LCAP)
                    list[w][p_] = (((ull)orf[u]) << 32) | (unsigned)(o + u * 32 + lane);
            }
        }
    }
    __syncwarp();

    const int c = scnt[w];          // exact count of cands with bin <= BA (>= 32)
    int* dst = g_nn + q * KNN;
    int B2; unsigned below2;
    ull* blist2 = (ull*)&hist[w][0];   // hist row dead after boundary scans

    if (c <= LCAP) {
        // ---- main path: re-histogram the small list -> exact boundary ----
        {
            uint4* hz = (uint4*)hist[w];
            uint4 z = make_uint4(0, 0, 0, 0);
#pragma unroll
            for (int i = lane; i < NBIN / 16; i += 32) hz[i] = z;
        }
        __syncwarp();

        const int rounds = (c + 31) / 32;
        for (int rd = 0; rd < rounds; ++rd) {
            int i = rd * 32 + lane;
            bool valid = i < c;
            unsigned mask = __ballot_sync(0xffffffffu, valid);
            if (valid) {
                unsigned bin = (unsigned)(list[w][i] >> (32 + ORD_SHIFT));
                unsigned mm = __match_any_sync(mask, bin);
                if ((mm & lt) == 0) {
                    int v = (int)hist[w][bin] + __popc(mm);
                    hist[w][bin] = (unsigned char)(v > 255 ? 255 : v);
                }
            }
        }
        __syncwarp();

        boundary_scan(hist[w], lane, B2, below2);   // exact global boundary

        // final collect from the list (hist row now reusable as blist2)
        for (int i = lane; i < c; i += 32) {
            ull key = list[w][i];
            unsigned bin = (unsigned)(key >> (32 + ORD_SHIFT));
            if (bin < (unsigned)B2) {
                dst[atomicAdd(&scnt2[w], 1)] = (int)(key & 0xffffffffu);
            } else if (bin == (unsigned)B2) {
                int p_ = atomicAdd(&bcnt2[w], 1);
                if (p_ < BLMAX) blist2[p_] = key;
            }
        }
    } else {
        // ---- fallback (P ~ 3e-5/warp): complete the histogram exactly ----
        hist_range(sp, hist[w], qx, qy, qz, qn, lane, lt, 1024, Npts);
        __syncwarp();

        boundary_scan(hist[w], lane, B2, below2);

        for (int o = 0; o < Npts; o += 256) {
            unsigned orf[8];
#pragma unroll
            for (int u = 0; u < 8; ++u) {
                float4 p = sp[o + u * 32 + lane];
                float d2 = fmaf(-2.0f, fmaf(qx, p.x, fmaf(qy, p.y, qz * p.z)), qn + p.w);
                orf[u] = ordflt(d2);
            }
#pragma unroll
            for (int u = 0; u < 8; ++u) {
                unsigned bin = orf[u] >> ORD_SHIFT;
                if (bin <= (unsigned)B2) {
                    int i = o + u * 32 + lane;
                    if (bin < (unsigned)B2) {
                        dst[atomicAdd(&scnt2[w], 1)] = i;
                    } else {
                        int p_ = atomicAdd(&bcnt2[w], 1);
                        if (p_ < BLMAX) blist2[p_] = (((ull)orf[u]) << 32) | (unsigned)i;
                    }
                }
            }
        }
    }
    __syncwarp();

    // ---------------- tail: extract r2 smallest from boundary bin ---------
    const int outn = scnt2[w];       // == below2
    const int brun = bcnt2[w];
    const int r2 = KNN - outn;

    if (brun <= BLMAX) {
        ull e[2];
#pragma unroll
        for (int t_ = 0; t_ < 2; ++t_) {
            int id = t_ * 32 + lane;
            e[t_] = (id < brun) ? blist2[id] : ~0ull;
        }
        for (int s_ = 0; s_ < r2; ++s_) {
            ull wm = e[0] < e[1] ? e[0] : e[1];
#pragma unroll
            for (int d_ = 16; d_ > 0; d_ >>= 1) {
                ull o = __shfl_xor_sync(0xffffffffu, wm, d_);
                wm = o < wm ? o : wm;
            }
            if (lane == 0) dst[outn + s_] = (int)(wm & 0xffffffffu);
#pragma unroll
            for (int t_ = 0; t_ < 2; ++t_)
                if (e[t_] == wm) e[t_] = ~0ull;
        }
    } else {
        // cold path (pathological tie density): ordered warp-min rescans
        ull last = 0ull;
        for (int s_ = 0; s_ < r2; ++s_) {
            ull best = ~0ull;
            for (int i = lane; i < Npts; i += 32) {
                float4 p = sp[i];
                float d2 = fmaf(-2.0f, fmaf(qx, p.x, fmaf(qy, p.y, qz * p.z)), qn + p.w);
                unsigned orf_ = ordflt(d2);
                if ((int)(orf_ >> ORD_SHIFT) == B2) {
                    ull key = (((ull)orf_) << 32) | (unsigned)i;
                    if (key > last && key < best) best = key;
                }
            }
#pragma unroll
            for (int d_ = 16; d_ > 0; d_ >>= 1) {
                ull o = __shfl_xor_sync(0xffffffffu, best, d_);
                best = o < best ? o : best;
            }
            if (lane == 0) dst[outn + s_] = (int)(best & 0xffffffffu);
            last = best;
        }
    }
}

// ---------------------------------------------------------------------------
// Precompute kernel: g_h1pre[n][j] = feat[n] @ W1[3:67] + b1   (pre-relu)
// Plain register-tiled GEMM, 128 rows/block, thread tile 4x8 with f32x2.
// ---------------------------------------------------------------------------
#define PRE_TPB 256

__global__ void __launch_bounds__(PRE_TPB)
pre_kernel(const float* __restrict__ feat,
           const float* __restrict__ W1,
           const float* __restrict__ b1)
{
    __shared__ __align__(16) float fT[CIN * 128];   // featT[c][row]  32 KB
    __shared__ __align__(16) float Wf[CIN * H1];    // W1 rows 3..66  16 KB

    const int t  = threadIdx.x;
    const int n0 = blockIdx.x * 128;

    // stage Wf: Wf[i] = W1[192 + i] (rows 3..66, linear)
    for (int i = t; i < CIN * H1 / 4; i += PRE_TPB)
        ((float4*)Wf)[i] = *(const float4*)(W1 + 192 + i * 4);

    // stage feat transposed
    {
        const int row  = t >> 1;
        const int half = t & 1;
        const float4* f4 = (const float4*)(feat + (size_t)(n0 + row) * CIN);
#pragma unroll
        for (int r_ = 0; r_ < 8; ++r_) {
            float4 v = f4[half * 8 + r_];
            int c0 = half * 32 + r_ * 4;
            fT[(c0 + 0) * 128 + row] = v.x;
            fT[(c0 + 1) * 128 + row] = v.y;
            fT[(c0 + 2) * 128 + row] = v.z;
            fT[(c0 + 3) * 128 + row] = v.w;
        }
    }
    __syncthreads();

    const int tk = t & 31;
    const int tj = t >> 5;

    ull acc[4][4];
    {
        float4 bA = ((const float4*)b1)[tj * 2];
        float4 bB = ((const float4*)b1)[tj * 2 + 1];
        ull bp[4] = { pack2(bA.x, bA.y), pack2(bA.z, bA.w),
                      pack2(bB.x, bB.y), pack2(bB.z, bB.w) };
#pragma unroll
        for (int r_ = 0; r_ < 4; ++r_)
#pragma unroll
            for (int p_ = 0; p_ < 4; ++p_) acc[r_][p_] = bp[p_];
    }

    for (int c = 0; c < CIN; ++c) {
        float4 xv = *(const float4*)&fT[c * 128 + tk * 4];
        ulonglong2 wA = *(const ulonglong2*)&Wf[c * H1 + tj * 8];
        ulonglong2 wB = *(const ulonglong2*)&Wf[c * H1 + tj * 8 + 4];
        ull x0 = pack2(xv.x, xv.x);
        ull x1 = pack2(xv.y, xv.y);
        ull x2 = pack2(xv.z, xv.z);
        ull x3 = pack2(xv.w, xv.w);
        acc[0][0] = fma2(x0, wA.x, acc[0][0]);
        acc[0][1] = fma2(x0, wA.y, acc[0][1]);
        acc[0][2] = fma2(x0, wB.x, acc[0][2]);
        acc[0][3] = fma2(x0, wB.y, acc[0][3]);
        acc[1][0] = fma2(x1, wA.x, acc[1][0]);
        acc[1][1] = fma2(x1, wA.y, acc[1][1]);
        acc[1][2] = fma2(x1, wB.x, acc[1][2]);
        acc[1][3] = fma2(x1, wB.y, acc[1][3]);
        acc[2][0] = fma2(x2, wA.x, acc[2][0]);
        acc[2][1] = fma2(x2, wA.y, acc[2][1]);
        acc[2][2] = fma2(x2, wB.x, acc[2][2]);
        acc[2][3] = fma2(x2, wB.y, acc[2][3]);
        acc[3][0] = fma2(x3, wA.x, acc[3][0]);
        acc[3][1] = fma2(x3, wA.y, acc[3][1]);
        acc[3][2] = fma2(x3, wB.x, acc[3][2]);
        acc[3][3] = fma2(x3, wB.y, acc[3][3]);
    }

#pragma unroll
    for (int r_ = 0; r_ < 4; ++r_)
#pragma unroll
        for (int p_ = 0; p_ < 4; ++p_)
            *(ull*)&g_h1pre[(size_t)(n0 + tk * 4 + r_) * H1 + tj * 8 + p_ * 2]
                = acc[r_][p_];
}

// ---------------------------------------------------------------------------
// MLP v3: gather precomputed h1_pre + xyz correction + relu, then phase-2
// register-tiled GEMM [128x64]@[64x128] with f32x2, max-pool epilogue.
// ---------------------------------------------------------------------------
#define MQPB    4
#define MLP_TPB 256

__global__ void __launch_bounds__(MLP_TPB, 2)
mlp_kernel(const float* __restrict__ pos,
           const float* __restrict__ W1,
           const float* __restrict__ W2,
           const float* __restrict__ b2,
           const void*  __restrict__ idxp,
           float* __restrict__ outp)
{
    __shared__ __align__(16) float W2s[H1 * H2];    // 32 KB
    __shared__ __align__(16) float h1T[H1 * 128];   // 32 KB; later redscr[32][129]
    __shared__ __align__(16) float W1x[3 * H1];     // xyz rows of W1

    const int t  = threadIdx.x;
    const int q0 = blockIdx.x * MQPB;
    const int b  = q0 >> 10;

    // ---- stage weights ----
    for (int i = t; i < H1 * H2 / 4; i += MLP_TPB)
        ((float4*)W2s)[i] = ((const float4*)W2)[i];
    if (t < 48) ((float4*)W1x)[t] = ((const float4*)W1)[t];
    __syncthreads();   // gather below reads W1x from smem

    // ---- gather h1_pre rows + xyz correction + relu, transposed store ----
    {
        const int row  = t >> 1;        // 0..127
        const int half = t & 1;
        const int lq   = row >> 5;
        const int k    = row & 31;
        const int q    = q0 + lq;

        const float* posb = pos + (size_t)b * Npts * 3;
        const int is64 = idx_is64(idxp);
        const long long qi = load_idx2(idxp, q, is64);
        const int n = g_nn[(size_t)q * KNN + k];

        const float x0 = posb[n * 3 + 0] - posb[qi * 3 + 0];
        const float x1 = posb[n * 3 + 1] - posb[qi * 3 + 1];
        const float x2 = posb[n * 3 + 2] - posb[qi * 3 + 2];

        const float4* pre4 = (const float4*)(g_h1pre + (size_t)((b << 12) + n) * H1);
#pragma unroll
        for (int r_ = 0; r_ < 8; ++r_) {
            float4 v = pre4[half * 8 + r_];
            int j0 = half * 32 + r_ * 4;
            float4 wx = *(const float4*)&W1x[j0];
            float4 wy = *(const float4*)&W1x[H1 + j0];
            float4 wz = *(const float4*)&W1x[2 * H1 + j0];
            v.x = fmaxf(fmaf(x0, wx.x, fmaf(x1, wy.x, fmaf(x2, wz.x, v.x))), 0.0f);
            v.y = fmaxf(fmaf(x0, wx.y, fmaf(x1, wy.y, fmaf(x2, wz.y, v.y))), 0.0f);
            v.z = fmaxf(fmaf(x0, wx.z, fmaf(x1, wy.z, fmaf(x2, wz.z, v.z))), 0.0f);
            v.w = fmaxf(fmaf(x0, wx.w, fmaf(x1, wy.w, fmaf(x2, wz.w, v.w))), 0.0f);
            h1T[(j0 + 0) * 128 + row] = v.x;
            h1T[(j0 + 1) * 128 + row] = v.y;
            h1T[(j0 + 2) * 128 + row] = v.z;
            h1T[(j0 + 3) * 128 + row] = v.w;
        }
    }
    __syncthreads();

    // ---- phase 2: tile 4 rows (tk) x 16 cols (td), f32x2 over d-pairs ----
    const int tk = t & 31;
    const int td = t >> 5;
    ull acc2[4][8];
#pragma unroll
    for (int r_ = 0; r_ < 4; ++r_)
#pragma unroll
        for (int p_ = 0; p_ < 8; ++p_) acc2[r_][p_] = 0ull;

    for (int j = 0; j < H1; ++j) {
        float4 hv = *(const float4*)&h1T[j * 128 + tk * 4];
        const ulonglong2* wp = (const ulonglong2*)&W2s[j * H2 + td * 16];
        ulonglong2 wA = wp[0], wB = wp[1], wC = wp[2], wD = wp[3];
        ull h0 = pack2(hv.x, hv.x);
        ull h1v = pack2(hv.y, hv.y);
        ull h2 = pack2(hv.z, hv.z);
        ull h3 = pack2(hv.w, hv.w);
        acc2[0][0] = fma2(h0, wA.x, acc2[0][0]);
        acc2[0][1] = fma2(h0, wA.y, acc2[0][1]);
        acc2[0][2] = fma2(h0, wB.x, acc2[0][2]);
        acc2[0][3] = fma2(h0, wB.y, acc2[0][3]);
        acc2[0][4] = fma2(h0, wC.x, acc2[0][4]);
        acc2[0][5] = fma2(h0, wC.y, acc2[0][5]);
        acc2[0][6] = fma2(h0, wD.x, acc2[0][6]);
        acc2[0][7] = fma2(h0, wD.y, acc2[0][7]);
        acc2[1][0] = fma2(h1v, wA.x, acc2[1][0]);
        acc2[1][1] = fma2(h1v, wA.y, acc2[1][1]);
        acc2[1][2] = fma2(h1v, wB.x, acc2[1][2]);
        acc2[1][3] = fma2(h1v, wB.y, acc2[1][3]);
        acc2[1][4] = fma2(h1v, wC.x, acc2[1][4]);
        acc2[1][5] = fma2(h1v, wC.y, acc2[1][5]);
        acc2[1][6] = fma2(h1v, wD.x, acc2[1][6]);
        acc2[1][7] = fma2(h1v, wD.y, acc2[1][7]);
        acc2[2][0] = fma2(h2, wA.x, acc2[2][0]);
        acc2[2][1] = fma2(h2, wA.y, acc2[2][1]);
        acc2[2][2] = fma2(h2, wB.x, acc2[2][2]);
        acc2[2][3] = fma2(h2, wB.y, acc2[2][3]);
        acc2[2][4] = fma2(h2, wC.x, acc2[2][4]);
        acc2[2][5] = fma2(h2, wC.y, acc2[2][5]);
        acc2[2][6] = fma2(h2, wD.x, acc2[2][6]);
        acc2[2][7] = fma2(h2, wD.y, acc2[2][7]);
        acc2[3][0] = fma2(h3, wA.x, acc2[3][0]);
        acc2[3][1] = fma2(h3, wA.y, acc2[3][1]);
        acc2[3][2] = fma2(h3, wB.x, acc2[3][2]);
        acc2[3][3] = fma2(h3, wB.y, acc2[3][3]);
        acc2[3][4] = fma2(h3, wC.x, acc2[3][4]);
        acc2[3][5] = fma2(h3, wC.y, acc2[3][5]);
        acc2[3][6] = fma2(h3, wD.x, acc2[3][6]);
        acc2[3][7] = fma2(h3, wD.y, acc2[3][7]);
    }
    __syncthreads();   // h1T reads done; reuse as reduction scratch

    // ---- epilogue: per-thread max over 4 rows, scratch, final reduce ----
    float* redscr = h1T;   // [32][129]
#pragma unroll
    for (int p_ = 0; p_ < 8; ++p_) {
        float e0, o0, e1, o1, e2, o2, e3, o3;
        unpack2(acc2[0][p_], e0, o0);
        unpack2(acc2[1][p_], e1, o1);
        unpack2(acc2[2][p_], e2, o2);
        unpack2(acc2[3][p_], e3, o3);
        float me = fmaxf(fmaxf(e0, e1), fmaxf(e2, e3));
        float mo = fmaxf(fmaxf(o0, o1), fmaxf(o2, o3));
        redscr[tk * 129 + td * 16 + p_ * 2 + 0] = me;
        redscr[tk * 129 + td * 16 + p_ * 2 + 1] = mo;
    }
    __syncthreads();

    for (int o = t; o < MQPB * H2; o += MLP_TPB) {
        int lq = o >> 7;
        int d  = o & 127;
        float mx = -FLT_MAX;
#pragma unroll
        for (int s_ = 0; s_ < 8; ++s_)
            mx = fmaxf(mx, redscr[(lq * 8 + s_) * 129 + d]);
        outp[(size_t)(q0 + lq) * H2 + d] = fmaxf(mx + b2[d], 0.0f);
    }
}

// ---------------------------------------------------------------------------
// launcher — knn first (ncu capture slot lands on it)
// ---------------------------------------------------------------------------
extern "C" void kernel_launch(void* const* d_in, const int* in_sizes, int n_in,
                              void* d_out, int out_size)
{
    const float* pos  = (const float*)d_in[0];   // [16,4096,3]
    const float* feat = (const float*)d_in[1];   // [16,4096,64]
    const float* W1   = (const float*)d_in[2];   // [67,64]
    const float* b1   = (const float*)d_in[3];   // [64]
    const float* W2   = (const float*)d_in[4];   // [64,128]
    const float* b2   = (const float*)d_in[5];   // [128]
    const void*  idxp = d_in[6];                 // [16,1024] int64 or int32

    float* out_posq = (float*)d_out;                          // 16*1024*3
    float* out_feat = (float*)d_out + (size_t)Bdim * Mq * 3;  // 16*1024*128

    knn_kernel<<<Bdim * (Mq / KQPB), KTPB>>>(pos, idxp, out_posq);

    pre_kernel<<<(Bdim * Npts) / 128, PRE_TPB>>>(feat, W1, b1);

    mlp_kernel<<<(Bdim * Mq) / MQPB, MLP_TPB>>>(pos, W1, W2, b2, idxp, out_feat);
}